// round 17
// baseline (speedup 1.0000x reference)
#include <cuda_runtime.h>
#include <cuda_fp16.h>
#include <cstdint>

// ---------------------------------------------------------------------------
// BarrierNet — all-MMA fp16, warp-specialized producer/consumer, v17.
//   (v16 + race fixes: producer-internal barrier, membar.cta before
//    produced-arrive, double-buffered u01/aw.)
//   CTA = 512 threads, 512 rows, four 128-row phases, 2 CTAs/SM.
//   Producers (warps 0-7) : layer-1 fp16 MMA -> bias -> f32 tanh-silu ->
//                           fp16x2 STS into X[ph&1]; obs prefetch (w0-3).
//   Consumers (warps 8-15): layer-2 fp16 MMA on X[ph&1] -> heads -> CBF.
//   Barriers: 1+b produced (prod arrive / cons sync, 512)
//             3+b consumed (cons arrive / prod sync, 512)
//             5 consumer-internal (256), 6 producer-internal (256)
// ---------------------------------------------------------------------------

typedef unsigned long long u64;
typedef unsigned int u32;

#define SM_X     0        // 2 x fp16 X [128 rows][256B] swizzled   65536
#define SM_WF    65536    // fp16 W2 [64 n][256B]                   16384
#define SM_A1    81920    // 2 x (128 rows x 48B) obs fp16 K=16     12288
#define SM_W1H   94208    // fp16 W1 [128 n][16 k] stride 48B        6144
#define SM_B1F   100352   // f32[128]
#define SM_W31   100864   // f32[64]
#define SM_W32   101120   // f32[32]
#define SM_SCAL  101248   // f32[4]
#define SM_B2F   101264   // f32[64]
#define SM_U01   101520   // 2 x float2[128]  2048
#define SM_AW    103568   // 2 x f32[128]     1024
#define SMEM_BYTES 104592

#define BAR_SYNC(id, n)   asm volatile("bar.sync %0, %1;"   :: "r"(id), "r"(n) : "memory")
#define BAR_ARRIVE(id, n) asm volatile("bar.arrive %0, %1;" :: "r"(id), "r"(n) : "memory")
#define MEMBAR_CTA()      asm volatile("membar.cta;" ::: "memory")

static __device__ __forceinline__ u32 smem_u32(const void* p) {
    u32 a;
    asm("{ .reg .u64 t; cvta.to.shared.u64 t, %1; cvt.u32.u64 %0, t; }"
        : "=r"(a) : "l"(p));
    return a;
}
static __device__ __forceinline__ float tanh_ap(float x) {
    float t; asm("tanh.approx.f32 %0, %1;" : "=f"(t) : "f"(x)); return t;
}
static __device__ __forceinline__ float fast_silu(float z) {
    return 0.5f * z * (1.0f + tanh_ap(0.5f * z));
}
static __device__ __forceinline__ float fast_sigmoid(float z) {
    return 0.5f * (1.0f + tanh_ap(0.5f * z));
}
static __device__ __forceinline__ u32 cvt_f16x2(float s1, float s0) {
    u32 d; asm("cvt.rn.f16x2.f32 %0, %1, %2;" : "=r"(d) : "f"(s1), "f"(s0));
    return d;
}
static __device__ __forceinline__ void ldsm4(u32* r, u32 addr) {
    asm volatile("ldmatrix.sync.aligned.m8n8.x4.shared.b16 {%0,%1,%2,%3}, [%4];"
        : "=r"(r[0]), "=r"(r[1]), "=r"(r[2]), "=r"(r[3]) : "r"(addr));
}
static __device__ __forceinline__ void sts32(u32 addr, u32 v) {
    asm volatile("st.shared.b32 [%0], %1;" :: "r"(addr), "r"(v) : "memory");
}
static __device__ __forceinline__ void mma_f16(float* d, const u32* a, u32 b0, u32 b1) {
    asm volatile("mma.sync.aligned.m16n8k16.row.col.f32.f16.f16.f32 "
        "{%0,%1,%2,%3}, {%4,%5,%6,%7}, {%8,%9}, {%0,%1,%2,%3};"
        : "+f"(d[0]), "+f"(d[1]), "+f"(d[2]), "+f"(d[3])
        : "r"(a[0]), "r"(a[1]), "r"(a[2]), "r"(a[3]), "r"(b0), "r"(b1));
}

__global__ void __launch_bounds__(512, 2)
barriernet_kernel(const float* __restrict__ obs,
                  const float* __restrict__ W1,  const float* __restrict__ b1,
                  const float* __restrict__ W21, const float* __restrict__ b21,
                  const float* __restrict__ W22, const float* __restrict__ b22,
                  const float* __restrict__ W31, const float* __restrict__ b31,
                  const float* __restrict__ W32, const float* __restrict__ b32,
                  float* __restrict__ out, int B)
{
    extern __shared__ char smc[];
    const u32 smb = smem_u32(smc);
    const int tid = threadIdx.x;

    float*  b1f  = reinterpret_cast<float*>(smc + SM_B1F);
    float*  b2f  = reinterpret_cast<float*>(smc + SM_B2F);
    float*  w31f = reinterpret_cast<float*>(smc + SM_W31);
    float*  w32f = reinterpret_cast<float*>(smc + SM_W32);
    float*  scal = reinterpret_cast<float*>(smc + SM_SCAL);

    const long long row_base = (long long)blockIdx.x * 512;

    // ------------------------------ staging ------------------------------
    for (int i = tid; i < 2048; i += 512) {              // W1 fp16 [128n][16k]
        int n = i >> 4, k = i & 15;
        __half v = (k < 10) ? __float2half(W1[n * 10 + k]) : __half(0.f);
        *reinterpret_cast<__half*>(smc + SM_W1H + n * 48 + k * 2) = v;
    }
    if (tid < 128) b1f[tid] = b1[tid];
    if (tid < 64) {
        b2f[tid]  = (tid < 32) ? b21[tid] : b22[tid - 32];
        w31f[tid] = W31[tid];                            // [2][32] row-major
    }
    if (tid < 32) w32f[tid] = W32[tid];
    if (tid == 0) { scal[0] = b31[0]; scal[1] = b31[1]; scal[2] = b32[0]; }

    for (int i = tid; i < 4096; i += 512) {              // W2 fp16 swizzled
        int n = i >> 6, kp = i & 63;
        const float* src = (n < 32) ? (W21 + n * 128 + 2 * kp)
                                    : (W22 + (n - 32) * 128 + 2 * kp);
        float2 w = *reinterpret_cast<const float2*>(src);
        u32 off = (u32)(n * 256) + (((u32)(4 * kp)) ^ ((u32)(n & 7) << 4));
        *reinterpret_cast<u32*>(smc + SM_WF + off) = cvt_f16x2(w.y, w.x);
    }

    // prologue: stage obs phase 0 -> A1[0]
    if (tid < 128) {
        const long long grow = row_base + tid;
        u32 h[8];
        if (grow < B) {
            const float2* q = reinterpret_cast<const float2*>(obs + grow * 10);
            float2 v0 = q[0], v1 = q[1], v2 = q[2], v3 = q[3], v4 = q[4];
            h[0] = cvt_f16x2(v0.y, v0.x); h[1] = cvt_f16x2(v1.y, v1.x);
            h[2] = cvt_f16x2(v2.y, v2.x); h[3] = cvt_f16x2(v3.y, v3.x);
            h[4] = cvt_f16x2(v4.y, v4.x);
        } else { h[0] = h[1] = h[2] = h[3] = h[4] = 0u; }
        h[5] = h[6] = h[7] = 0u;
        char* a1 = smc + SM_A1 + tid * 48;
        *reinterpret_cast<uint4*>(a1)      = make_uint4(h[0], h[1], h[2], h[3]);
        *reinterpret_cast<uint4*>(a1 + 16) = make_uint4(h[4], h[5], h[6], h[7]);
    }
    __syncthreads();

    const int wid = tid >> 5, lane = tid & 31;
    const int gid = lane >> 2, tig = lane & 3;
    const int g8  = lane >> 3, r8 = lane & 7;

    if (wid < 8) {
        // ========================== PRODUCERS (warps 0-7) ==========================
        const int mg = wid & 3;
        const int nh = wid >> 2;
        const int arow1 = mg * 32 + ((g8 & 1) << 3) + r8;
        const u32 aOff1 = (u32)arow1 * 48 + ((u32)(g8 >> 1) << 4);
        const u32 w1base = smb + SM_W1H
                         + (u32)((((g8 >> 1) << 3) + r8) * 48) + ((u32)(g8 & 1) << 4);

        #pragma unroll 1
        for (int ph = 0; ph < 4; ph++) {
            const int b = ph & 1;
            if (ph > 0)  BAR_SYNC(6, 256);               // producer-internal: A1 ready
            if (ph >= 2) BAR_SYNC(3 + b, 512);           // X[b] consumed

            const u32 a1b = smb + SM_A1 + (u32)(b * 6144);
            const u32 xbuf = smb + SM_X + (u32)(b * 32768);
            u32 af0[4], af1[4];
            ldsm4(af0, a1b + aOff1);
            ldsm4(af1, a1b + aOff1 + 16 * 48);
            #pragma unroll
            for (int hf = 0; hf < 2; hf++) {
                float acc[2][4][4];
                #pragma unroll
                for (int m = 0; m < 2; m++)
                    #pragma unroll
                    for (int nt = 0; nt < 4; nt++)
                        #pragma unroll
                        for (int c = 0; c < 4; c++) acc[m][nt][c] = 0.f;
                u32 bf[2][4];
                ldsm4(bf[0], w1base + (u32)((nh * 64 + hf * 32)      * 48));
                ldsm4(bf[1], w1base + (u32)((nh * 64 + hf * 32 + 16) * 48));
                #pragma unroll
                for (int nt = 0; nt < 4; nt++) {
                    u32 b0  = bf[nt >> 1][(nt & 1) * 2];
                    u32 b1v = bf[nt >> 1][(nt & 1) * 2 + 1];
                    mma_f16(acc[0][nt], af0, b0, b1v);
                    mma_f16(acc[1][nt], af1, b0, b1v);
                }
                #pragma unroll
                for (int m = 0; m < 2; m++) {
                    const int r0 = mg * 32 + m * 16 + gid;
                    const u32 swr = ((u32)(r0 & 7)) << 4;
                    const u32 xb0 = xbuf + (u32)r0 * 256;
                    #pragma unroll
                    for (int nt = 0; nt < 4; nt++) {
                        const int col = nh * 64 + hf * 32 + nt * 8 + 2 * tig;
                        const float2 bb = *reinterpret_cast<const float2*>(b1f + col);
                        u32 v0 = cvt_f16x2(fast_silu(acc[m][nt][1] + bb.y),
                                           fast_silu(acc[m][nt][0] + bb.x));
                        u32 v1 = cvt_f16x2(fast_silu(acc[m][nt][3] + bb.y),
                                           fast_silu(acc[m][nt][2] + bb.x));
                        const u32 co = ((u32)(2 * col)) ^ swr;
                        sts32(xb0 + co, v0);
                        sts32(xb0 + 8 * 256 + co, v1);
                    }
                }
            }
            MEMBAR_CTA();                                // STS visible before arrive
            BAR_ARRIVE(1 + b, 512);                      // X[b] produced

            if (ph < 3 && tid < 128) {                   // prefetch next obs
                const long long grow = row_base + (ph + 1) * 128 + tid;
                u32 h[8];
                if (grow < B) {
                    const float2* q = reinterpret_cast<const float2*>(obs + grow * 10);
                    float2 v0 = q[0], v1 = q[1], v2 = q[2], v3 = q[3], v4 = q[4];
                    h[0] = cvt_f16x2(v0.y, v0.x); h[1] = cvt_f16x2(v1.y, v1.x);
                    h[2] = cvt_f16x2(v2.y, v2.x); h[3] = cvt_f16x2(v3.y, v3.x);
                    h[4] = cvt_f16x2(v4.y, v4.x);
                } else { h[0] = h[1] = h[2] = h[3] = h[4] = 0u; }
                h[5] = h[6] = h[7] = 0u;
                char* a1 = smc + SM_A1 + ((ph + 1) & 1) * 6144 + tid * 48;
                *reinterpret_cast<uint4*>(a1)      = make_uint4(h[0], h[1], h[2], h[3]);
                *reinterpret_cast<uint4*>(a1 + 16) = make_uint4(h[4], h[5], h[6], h[7]);
            }
        }
    } else {
        // ========================== CONSUMERS (warps 8-15) ==========================
        const int cwid = wid - 8;
        const int ctid = tid - 256;
        const int mg = cwid & 3;
        const int nh = cwid >> 2;
        const u32 swz    = (u32)r8 << 4;
        const u32 a_koff = (u32)((g8 >> 1) << 4);
        const int arow0  = mg * 32 + ((g8 & 1) << 3) + r8;
        const u32 aOff0  = (u32)arow0 * 256;
        const u32 b_noff = (u32)(((g8 >> 1) << 3) + r8);
        const u32 b_koff = (u32)((g8 & 1) << 4);
        u32 bFb[2];
        #pragma unroll
        for (int g = 0; g < 2; g++) {
            u32 n = (u32)(nh * 32 + g * 16) + b_noff;
            bFb[g] = smb + SM_WF + n * 256;
        }

        #pragma unroll 1
        for (int ph = 0; ph < 4; ph++) {
            const int b = ph & 1;
            BAR_SYNC(1 + b, 512);                        // X[b] produced

            const u32 aF0 = smb + SM_X + (u32)(b * 32768) + aOff0;
            const u32 aF1 = aF0 + 16 * 256;
            float acc[2][4][4];
            #pragma unroll
            for (int m = 0; m < 2; m++)
                #pragma unroll
                for (int nt = 0; nt < 4; nt++)
                    #pragma unroll
                    for (int c = 0; c < 4; c++) acc[m][nt][c] = 0.f;

            #pragma unroll 2
            for (int ks = 0; ks < 8; ks++) {
                const u32 kbyte = (u32)(32 * ks);
                const u32 ka = (kbyte + a_koff) ^ swz;
                const u32 kb = (kbyte + b_koff) ^ swz;
                u32 a0[4], a1v[4], bf0[4], bf1[4];
                ldsm4(a0, aF0 + ka);
                ldsm4(a1v, aF1 + ka);
                ldsm4(bf0, bFb[0] + kb);
                ldsm4(bf1, bFb[1] + kb);
                #pragma unroll
                for (int nt = 0; nt < 4; nt++) {
                    u32 b0 = (nt < 2 ? bf0 : bf1)[(nt & 1) * 2];
                    u32 b1v = (nt < 2 ? bf0 : bf1)[(nt & 1) * 2 + 1];
                    mma_f16(acc[0][nt], a0, b0, b1v);
                    mma_f16(acc[1][nt], a1v, b0, b1v);
                }
            }
            BAR_ARRIVE(3 + b, 512);                      // X[b] consumed

            float2* u01 = reinterpret_cast<float2*>(smc + SM_U01 + b * 1024);
            float*  awb = reinterpret_cast<float*>(smc + SM_AW + b * 512);

            // ---- heads partials ----
            float p0[4] = {0.f, 0.f, 0.f, 0.f};
            float p1[4] = {0.f, 0.f, 0.f, 0.f};
            #pragma unroll
            for (int m = 0; m < 2; m++)
                #pragma unroll
                for (int nt = 0; nt < 4; nt++)
                    #pragma unroll
                    for (int c = 0; c < 2; c++) {
                        const int col = nh * 32 + nt * 8 + 2 * tig + c;
                        const float bias = b2f[col];
                        const float vlo = fast_silu(acc[m][nt][c] + bias);
                        const float vhi = fast_silu(acc[m][nt][2 + c] + bias);
                        if (nh == 0) {
                            const float wA = w31f[col], wB = w31f[32 + col];
                            p0[2 * m]     += vlo * wA; p1[2 * m]     += vlo * wB;
                            p0[2 * m + 1] += vhi * wA; p1[2 * m + 1] += vhi * wB;
                        } else {
                            const float wC = w32f[col - 32];
                            p0[2 * m]     += vlo * wC;
                            p0[2 * m + 1] += vhi * wC;
                        }
                    }
            #pragma unroll
            for (int i = 0; i < 4; i++) {
                p0[i] += __shfl_xor_sync(0xFFFFFFFFu, p0[i], 1);
                p0[i] += __shfl_xor_sync(0xFFFFFFFFu, p0[i], 2);
                if (nh == 0) {
                    p1[i] += __shfl_xor_sync(0xFFFFFFFFu, p1[i], 1);
                    p1[i] += __shfl_xor_sync(0xFFFFFFFFu, p1[i], 2);
                }
            }
            {
                const int row = mg * 32 + gid + tig * 8;
                const float s0 = (tig == 0) ? p0[0] : (tig == 1) ? p0[1]
                               : (tig == 2) ? p0[2] : p0[3];
                if (nh == 0) {
                    const float s1 = (tig == 0) ? p1[0] : (tig == 1) ? p1[1]
                                   : (tig == 2) ? p1[2] : p1[3];
                    u01[row] = make_float2(s0, s1);
                } else {
                    awb[row] = s0;
                }
            }
            BAR_SYNC(5, 256);                            // u01/aw visible (consumers)

            if (ctid < 128) {
                const long long grow = row_base + ph * 128 + ctid;
                if (grow < B) {
                    float2 uv = u01[ctid];
                    const float u0 = uv.x + scal[0];
                    const float u1 = uv.y + scal[1];
                    const float aw = awb[ctid] + scal[2];
                    const float2* pp = reinterpret_cast<const float2*>(obs + grow * 10 + 6);
                    const float2 rv = pp[0], vv = pp[1];
                    const float alpha   = 4.0f * fast_sigmoid(aw);
                    const float barrier = rv.x * rv.x + rv.y * rv.y - 0.64f;
                    const float lf      = -2.0f * (rv.x * vv.x + rv.y * vv.y);
                    const float Gx = -2.0f * rv.x, Gy = -2.0f * rv.y;
                    const float hh   = lf + alpha * barrier;
                    const float gg   = Gx * Gx + Gy * Gy;
                    const float viol = Gx * u0 + Gy * u1 - hh;
                    const float lam  = (gg > 0.0f)
                        ? __fdividef(fmaxf(viol, 0.0f), fmaxf(gg, 1e-12f))
                        : 0.0f;
                    reinterpret_cast<float2*>(out)[grow] =
                        make_float2(u0 - lam * Gx, u1 - lam * Gy);
                }
            }
        }
    }
}

extern "C" void kernel_launch(void* const* d_in, const int* in_sizes, int n_in,
                              void* d_out, int out_size)
{
    const float* obs = (const float*)d_in[0];
    const float* W1  = (const float*)d_in[1];
    const float* b1  = (const float*)d_in[2];
    const float* W21 = (const float*)d_in[3];
    const float* b21 = (const float*)d_in[4];
    const float* W22 = (const float*)d_in[5];
    const float* b22 = (const float*)d_in[6];
    const float* W31 = (const float*)d_in[7];
    const float* b31 = (const float*)d_in[8];
    const float* W32 = (const float*)d_in[9];
    const float* b32 = (const float*)d_in[10];
    float* out = (float*)d_out;

    int B = in_sizes[0] / 10;

    cudaFuncSetAttribute(barriernet_kernel,
                         cudaFuncAttributeMaxDynamicSharedMemorySize, SMEM_BYTES);

    int blocks = (B + 511) / 512;
    barriernet_kernel<<<blocks, 512, SMEM_BYTES>>>(
        obs, W1, b1, W21, b21, W22, b22, W31, b31, W32, b32, out, B);
}